// round 4
// baseline (speedup 1.0000x reference)
#include <cuda_runtime.h>
#include <math.h>
#include <stdint.h>

#define NP 65536
#define EPSF 1e-6f

// ---------------- scratch (static device allocations; no cudaMalloc) -------------
__device__ float g_q0 [2*128*NP];   // conv1x1(edge, Wq)
__device__ float g_kv0[2*256*NP];   // conv1x1(x, Wkv)
__device__ float g_q  [2*32*NP*8];  // sigmoid(q)  [b][h][n][d]
__device__ float g_k  [2*32*NP*8];  // sigmoid(k)
__device__ float g_v  [2*32*NP*8];  // v (raw)
__device__ float g_stats[64*128];   // per (b,h): [0:8) qsum [8:16) ksum [16:24) qsi [24:32) kso [32] Z [40:104) kvm
__device__ float g_hstats[64*80];   // packed per (b,h): [0:64) kvm*n/Z  [64:72) ksum  [72:80) kso

__device__ __forceinline__ float sigmoidf_(float x){
    return __fdividef(1.f, 1.f + __expf(-x));
}

// ---------------- zero stats -------------
__global__ void k_zero(float* __restrict__ p, int n){
    int i = blockIdx.x*blockDim.x + threadIdx.x;
    if (i < n) p[i] = 0.f;
}

// ---------------- tiled fp32 GEMM for conv1x1: Y[b][m][p] = sum_k A[m][k]*X[b][k][p] ---
__global__ __launch_bounds__(256) void k_gemm(
    const float* __restrict__ A, const float* __restrict__ X, float* __restrict__ Y,
    int M, int K)
{
    __shared__ float Ws[8][128];
    __shared__ float Xs[8][128];
    const int b  = blockIdx.z;
    const int m0 = blockIdx.y * 128;
    const int p0 = blockIdx.x * 128;
    const float* Xb = X + (size_t)b * K * NP;
    float*       Yb = Y + (size_t)b * M * NP;
    const int tid = threadIdx.x;
    const int ty = tid >> 4;
    const int tx = tid & 15;

    float acc[8][8];
    #pragma unroll
    for (int i = 0; i < 8; i++)
        #pragma unroll
        for (int j = 0; j < 8; j++) acc[i][j] = 0.f;

    for (int k0 = 0; k0 < K; k0 += 8) {
        {
            int r = tid >> 1;
            int c = (tid & 1) * 4;
            float4 w4 = *(const float4*)&A[(size_t)(m0 + r) * K + k0 + c];
            Ws[c+0][r] = w4.x; Ws[c+1][r] = w4.y; Ws[c+2][r] = w4.z; Ws[c+3][r] = w4.w;
        }
        {
            int r = tid >> 5;
            int c = (tid & 31) * 4;
            *(float4*)&Xs[r][c] = *(const float4*)&Xb[(size_t)(k0 + r) * NP + p0 + c];
        }
        __syncthreads();
        #pragma unroll
        for (int kk = 0; kk < 8; kk++) {
            float a[8], bb[8];
            *(float4*)(a)   = *(const float4*)&Ws[kk][ty*8];
            *(float4*)(a+4) = *(const float4*)&Ws[kk][ty*8+4];
            *(float4*)(bb)  = *(const float4*)&Xs[kk][tx*8];
            *(float4*)(bb+4)= *(const float4*)&Xs[kk][tx*8+4];
            #pragma unroll
            for (int i = 0; i < 8; i++)
                #pragma unroll
                for (int j = 0; j < 8; j++)
                    acc[i][j] = fmaf(a[i], bb[j], acc[i][j]);
        }
        __syncthreads();
    }

    #pragma unroll
    for (int i = 0; i < 8; i++) {
        int m = m0 + ty*8 + i;
        float* dst = &Yb[(size_t)m * NP + p0 + tx*8];
        *(float4*)(dst)   = make_float4(acc[i][0], acc[i][1], acc[i][2], acc[i][3]);
        *(float4*)(dst+4) = make_float4(acc[i][4], acc[i][5], acc[i][6], acc[i][7]);
    }
}

// ---------------- fused q build: dw5x5 + gconv + sigmoid + qsum --------------------
__global__ __launch_bounds__(256) void k_fq(
    const float* __restrict__ q0, const float* __restrict__ dwq,
    const float* __restrict__ pwq, float* __restrict__ qout, float* __restrict__ stats)
{
    const int g = blockIdx.z & 15;
    const int b = blockIdx.z >> 4;
    const int x0 = blockIdx.x * 32, y0 = blockIdx.y * 32;
    __shared__ float sm[8][36][40];
    __shared__ float pw[64];
    __shared__ float kwsm[200];
    __shared__ float red[128];
    const int tid = threadIdx.y * 32 + threadIdx.x;
    if (tid < 64)  pw[tid]   = pwq[g*64 + tid];
    if (tid < 200) kwsm[tid] = dwq[g*200 + tid];

    const float* base = q0 + (size_t)(b*128 + g*8) * NP;
    for (int idx = tid; idx < 8*36*36; idx += 256) {
        int c   = idx / 1296;
        int rem = idx - c*1296;
        int r   = rem / 36;
        int col = rem - r*36;
        int gy = y0 + r - 2, gx = x0 + col - 2;
        float v = 0.f;
        if ((unsigned)gy < 256u && (unsigned)gx < 256u)
            v = base[(size_t)c*NP + gy*256 + gx];
        sm[c][r][col] = v;
    }
    __syncthreads();

    const int tx = threadIdx.x;
    const int ly0 = threadIdx.y * 4;

    float dwv[8][4];
    #pragma unroll
    for (int c = 0; c < 8; c++) {
        float kw[25];
        #pragma unroll
        for (int t = 0; t < 25; t++) kw[t] = kwsm[c*25 + t];
        float a0=0.f,a1=0.f,a2=0.f,a3=0.f;
        #pragma unroll
        for (int r = 0; r < 8; r++) {
            float v0 = sm[c][ly0+r][tx+0];
            float v1 = sm[c][ly0+r][tx+1];
            float v2 = sm[c][ly0+r][tx+2];
            float v3 = sm[c][ly0+r][tx+3];
            float v4 = sm[c][ly0+r][tx+4];
            #pragma unroll
            for (int j = 0; j < 4; j++) {
                int ky = r - j;
                if (ky >= 0 && ky < 5) {
                    float s = kw[ky*5+0]*v0 + kw[ky*5+1]*v1 + kw[ky*5+2]*v2
                            + kw[ky*5+3]*v3 + kw[ky*5+4]*v4;
                    if (j == 0) a0 += s; else if (j == 1) a1 += s;
                    else if (j == 2) a2 += s; else a3 += s;
                }
            }
        }
        dwv[c][0]=a0; dwv[c][1]=a1; dwv[c][2]=a2; dwv[c][3]=a3;
    }

    float sdir[8], sms[8];
    #pragma unroll
    for (int d = 0; d < 8; d++) { sdir[d]=0.f; sms[d]=0.f; }

    #pragma unroll
    for (int j = 0; j < 4; j++) {
        int n = (y0 + ly0 + j) * 256 + x0 + tx;
        float dir[8], msd[8];
        #pragma unroll
        for (int d = 0; d < 8; d++) {
            dir[d] = sigmoidf_(sm[d][ly0+j+2][tx+2]);
            float s = 0.f;
            #pragma unroll
            for (int i = 0; i < 8; i++) s = fmaf(pw[d*8+i], dwv[i][j], s);
            msd[d] = sigmoidf_(s);
            sdir[d] += dir[d];
            sms[d]  += msd[d];
        }
        float4* d0 = (float4*)&qout[((size_t)(b*32 + g) * NP + n) * 8];
        d0[0] = make_float4(dir[0],dir[1],dir[2],dir[3]);
        d0[1] = make_float4(dir[4],dir[5],dir[6],dir[7]);
        float4* d1 = (float4*)&qout[((size_t)(b*32 + 16 + g) * NP + n) * 8];
        d1[0] = make_float4(msd[0],msd[1],msd[2],msd[3]);
        d1[1] = make_float4(msd[4],msd[5],msd[6],msd[7]);
    }

    float vals[16];
    #pragma unroll
    for (int d = 0; d < 8; d++) { vals[d] = sdir[d]; vals[8+d] = sms[d]; }
    #pragma unroll
    for (int i = 0; i < 16; i++)
        for (int off = 16; off; off >>= 1) vals[i] += __shfl_down_sync(~0u, vals[i], off);
    int lane = tid & 31, w = tid >> 5;
    if (lane == 0)
        #pragma unroll
        for (int i = 0; i < 16; i++) red[w*16 + i] = vals[i];
    __syncthreads();
    if (tid < 16) {
        float t = 0.f;
        #pragma unroll
        for (int w2 = 0; w2 < 8; w2++) t += red[w2*16 + tid];
        int h = (tid < 8) ? g : (16 + g);
        atomicAdd(&stats[(b*32 + h)*128 + (tid & 7)], t);
    }
}

// ---------------- fused kv build: dw5x5 + gconv, k=sigmoid+ksum, v raw -------------
__global__ __launch_bounds__(256) void k_fkv(
    const float* __restrict__ kv0, const float* __restrict__ dwkv,
    const float* __restrict__ pwkv, float* __restrict__ kout, float* __restrict__ vout,
    float* __restrict__ stats)
{
    const int g = blockIdx.z & 15;
    const int b = blockIdx.z >> 4;
    const int x0 = blockIdx.x * 32, y0 = blockIdx.y * 32;
    __shared__ float sm[8][36][40];
    __shared__ float pw[128];
    __shared__ float kwsm[400];
    __shared__ float red[128];
    const int tid = threadIdx.y * 32 + threadIdx.x;
    if (tid < 128) pw[tid] = pwkv[g*128 + tid];
    for (int t = tid; t < 400; t += 256) kwsm[t] = dwkv[g*400 + t];

    const int tx = threadIdx.x;
    const int ly0 = threadIdx.y * 4;
    float ksum[16];
    #pragma unroll
    for (int i = 0; i < 16; i++) ksum[i] = 0.f;

    #pragma unroll
    for (int half = 0; half < 2; half++) {
        const float* base = kv0 + (size_t)(b*256 + g*16 + half*8) * NP;
        __syncthreads();
        for (int idx = tid; idx < 8*36*36; idx += 256) {
            int c   = idx / 1296;
            int rem = idx - c*1296;
            int r   = rem / 36;
            int col = rem - r*36;
            int gy = y0 + r - 2, gx = x0 + col - 2;
            float v = 0.f;
            if ((unsigned)gy < 256u && (unsigned)gx < 256u)
                v = base[(size_t)c*NP + gy*256 + gx];
            sm[c][r][col] = v;
        }
        __syncthreads();

        float dwv[8][4];
        #pragma unroll
        for (int c = 0; c < 8; c++) {
            float kw[25];
            #pragma unroll
            for (int t = 0; t < 25; t++) kw[t] = kwsm[half*200 + c*25 + t];
            float a0=0.f,a1=0.f,a2=0.f,a3=0.f;
            #pragma unroll
            for (int r = 0; r < 8; r++) {
                float v0 = sm[c][ly0+r][tx+0];
                float v1 = sm[c][ly0+r][tx+1];
                float v2 = sm[c][ly0+r][tx+2];
                float v3 = sm[c][ly0+r][tx+3];
                float v4 = sm[c][ly0+r][tx+4];
                #pragma unroll
                for (int j = 0; j < 4; j++) {
                    int ky = r - j;
                    if (ky >= 0 && ky < 5) {
                        float s = kw[ky*5+0]*v0 + kw[ky*5+1]*v1 + kw[ky*5+2]*v2
                                + kw[ky*5+3]*v3 + kw[ky*5+4]*v4;
                        if (j == 0) a0 += s; else if (j == 1) a1 += s;
                        else if (j == 2) a2 += s; else a3 += s;
                    }
                }
            }
            dwv[c][0]=a0; dwv[c][1]=a1; dwv[c][2]=a2; dwv[c][3]=a3;
        }

        float* out = half == 0 ? kout : vout;
        #pragma unroll
        for (int j = 0; j < 4; j++) {
            int n = (y0 + ly0 + j) * 256 + x0 + tx;
            float dir[8], msd[8];
            #pragma unroll
            for (int d = 0; d < 8; d++) {
                float dv = sm[d][ly0+j+2][tx+2];
                float s = 0.f;
                #pragma unroll
                for (int i = 0; i < 8; i++) s = fmaf(pw[half*64 + d*8+i], dwv[i][j], s);
                if (half == 0) {
                    dv = sigmoidf_(dv); s = sigmoidf_(s);
                    ksum[d] += dv; ksum[8+d] += s;
                }
                dir[d] = dv; msd[d] = s;
            }
            float4* d0 = (float4*)&out[((size_t)(b*32 + g) * NP + n) * 8];
            d0[0] = make_float4(dir[0],dir[1],dir[2],dir[3]);
            d0[1] = make_float4(dir[4],dir[5],dir[6],dir[7]);
            float4* d1 = (float4*)&out[((size_t)(b*32 + 16 + g) * NP + n) * 8];
            d1[0] = make_float4(msd[0],msd[1],msd[2],msd[3]);
            d1[1] = make_float4(msd[4],msd[5],msd[6],msd[7]);
        }
    }

    #pragma unroll
    for (int i = 0; i < 16; i++)
        for (int off = 16; off; off >>= 1) ksum[i] += __shfl_down_sync(~0u, ksum[i], off);
    int lane = tid & 31, w = tid >> 5;
    if (lane == 0)
        #pragma unroll
        for (int i = 0; i < 16; i++) red[w*16 + i] = ksum[i];
    __syncthreads();
    if (tid < 16) {
        float t = 0.f;
        #pragma unroll
        for (int w2 = 0; w2 < 8; w2++) t += red[w2*16 + tid];
        int h = (tid < 8) ? g : (16 + g);
        atomicAdd(&stats[(b*32 + h)*128 + 8 + (tid & 7)], t);
    }
}

// ---------------- sink_incoming/source_outgoing reductions --------
__global__ __launch_bounds__(256) void k_siso(
    const float* __restrict__ q, const float* __restrict__ k, float* __restrict__ stats)
{
    const int h = blockIdx.y, b = blockIdx.z;
    const int bh = b*32 + h;
    const int tid = threadIdx.x;
    __shared__ float qs[8], ks[8];
    __shared__ float red[128];
    if (tid < 8)  qs[tid] = stats[bh*128 + tid];
    else if (tid < 16) ks[tid-8] = stats[bh*128 + tid];
    __syncthreads();

    float aq[8], ak[8];
    #pragma unroll
    for (int d = 0; d < 8; d++) { aq[d] = 0.f; ak[d] = 0.f; }
    const int nbase = blockIdx.x * 1024;

    for (int it = 0; it < 4; it++) {
        int n = nbase + it*256 + tid;
        size_t base = ((size_t)bh * NP + n) * 8;
        float qv[8], kv_[8];
        *(float4*)(qv)    = *(const float4*)&q[base];
        *(float4*)(qv+4)  = *(const float4*)&q[base+4];
        *(float4*)(kv_)   = *(const float4*)&k[base];
        *(float4*)(kv_+4) = *(const float4*)&k[base+4];
        float s1 = EPSF, s2 = EPSF;
        #pragma unroll
        for (int d = 0; d < 8; d++) {
            s1 = fmaf(qv[d] + EPSF, ks[d] + EPSF, s1);
            s2 = fmaf(kv_[d] + EPSF, qs[d] + EPSF, s2);
        }
        float siv = 1.f / s1;
        float sov = 1.f / s2;
        #pragma unroll
        for (int d = 0; d < 8; d++) { aq[d] = fmaf(qv[d], siv, aq[d]); ak[d] = fmaf(kv_[d], sov, ak[d]); }
    }
    float vals[16];
    #pragma unroll
    for (int d = 0; d < 8; d++) { vals[d] = aq[d]; vals[8+d] = ak[d]; }
    #pragma unroll
    for (int i = 0; i < 16; i++)
        for (int off = 16; off; off >>= 1) vals[i] += __shfl_down_sync(~0u, vals[i], off);
    int lane = tid & 31, w = tid >> 5;
    if (lane == 0)
        #pragma unroll
        for (int i = 0; i < 16; i++) red[w*16 + i] = vals[i];
    __syncthreads();
    if (tid < 16) {
        float t = 0.f;
        #pragma unroll
        for (int w2 = 0; w2 < 8; w2++) t += red[w2*16 + tid];
        atomicAdd(&stats[bh*128 + 16 + tid], t);
    }
}

// ---------------- Z and kvm accumulation ----------------
__global__ __launch_bounds__(256) void k_kvm(
    const float* __restrict__ k, const float* __restrict__ v, float* __restrict__ stats)
{
    const int h = blockIdx.y, b = blockIdx.z;
    const int bh = b*32 + h;
    const int tid = threadIdx.x;
    __shared__ float qsi[8];
    __shared__ float red[8*65];
    if (tid < 8) qsi[tid] = stats[bh*128 + 16 + tid];
    __syncthreads();

    float acc[64];
    #pragma unroll
    for (int i = 0; i < 64; i++) acc[i] = 0.f;
    float zl = 0.f;
    const int nbase = blockIdx.x * 8192;

    for (int it = 0; it < 32; it++) {
        int n = nbase + it*256 + tid;
        size_t base = ((size_t)bh * NP + n) * 8;
        float kv_[8], vv[8];
        *(float4*)(kv_)   = *(const float4*)&k[base];
        *(float4*)(kv_+4) = *(const float4*)&k[base+4];
        *(float4*)(vv)    = *(const float4*)&v[base];
        *(float4*)(vv+4)  = *(const float4*)&v[base+4];
        float cs = EPSF;
        #pragma unroll
        for (int d = 0; d < 8; d++) cs = fmaf(kv_[d] + EPSF, qsi[d] + EPSF, cs);
        cs = fminf(fmaxf(cs, -1.f), 1.f);
        float ex = __expf(cs);
        zl += ex;
        #pragma unroll
        for (int e = 0; e < 8; e++) {
            float ve = vv[e] * ex;
            #pragma unroll
            for (int d = 0; d < 8; d++)
                acc[d*8 + e] = fmaf(kv_[d], ve, acc[d*8 + e]);
        }
    }
    #pragma unroll
    for (int i = 0; i < 64; i++)
        for (int off = 16; off; off >>= 1) acc[i] += __shfl_down_sync(~0u, acc[i], off);
    for (int off = 16; off; off >>= 1) zl += __shfl_down_sync(~0u, zl, off);
    int lane = tid & 31, w = tid >> 5;
    if (lane == 0) {
        #pragma unroll
        for (int i = 0; i < 64; i++) red[w*65 + i] = acc[i];
        red[w*65 + 64] = zl;
    }
    __syncthreads();
    if (tid < 65) {
        float t = 0.f;
        #pragma unroll
        for (int w2 = 0; w2 < 8; w2++) t += red[w2*65 + tid];
        atomicAdd(&stats[bh*128 + (tid < 64 ? 40 + tid : 32)], t);
    }
}

// ---------------- pack per-head constants for the fused proj GEMM -------------
__global__ void k_prep(const float* __restrict__ stats, float* __restrict__ hstats)
{
    int bh = blockIdx.x;          // 0..63
    int t  = threadIdx.x;         // 0..79
    float v;
    if (t < 64) {
        float z = stats[bh*128 + 32];
        v = stats[bh*128 + 40 + t] * (65536.f / z);
    } else if (t < 72) {
        v = stats[bh*128 + 8 + (t - 64)];     // ksum
    } else {
        v = stats[bh*128 + 24 + (t - 72)];    // kso
    }
    hstats[bh*80 + t] = v;
}

// ---------------- fused projection GEMM: computes o on the fly from q + stats -----
// out[b][m][p] = BN( sum_{h,e} Wp[m][h*8+e] * LN(q-attn-out)[b][h][p][e] )
__global__ __launch_bounds__(256) void k_gemm_proj(
    const float* __restrict__ Wp, const float* __restrict__ q,
    const float* __restrict__ hstats,
    const float* __restrict__ ln_g, const float* __restrict__ ln_b,
    const float* __restrict__ bng, const float* __restrict__ bnb,
    const float* __restrict__ bnm, const float* __restrict__ bnv,
    float* __restrict__ Y)
{
    __shared__ float Ws[8][128];
    __shared__ float Xs[8][128];
    __shared__ float hs[80];
    __shared__ float lg[8], lb[8];
    const int b  = blockIdx.z;
    const int p0 = blockIdx.x * 128;
    const int tid = threadIdx.x;
    const int ty = tid >> 4;
    const int tx = tid & 15;
    if (tid < 8) { lg[tid] = ln_g[tid]; lb[tid] = ln_b[tid]; }

    float acc[8][8];
    #pragma unroll
    for (int i = 0; i < 8; i++)
        #pragma unroll
        for (int j = 0; j < 8; j++) acc[i][j] = 0.f;

    for (int h = 0; h < 32; h++) {
        const int bh = b*32 + h;
        __syncthreads();   // protect hs/Xs/Ws from previous iteration's readers
        if (tid < 80) hs[tid] = hstats[bh*80 + tid];
        if (tid >= 128) {
            // load Wp tile: Ws[c][m] = Wp[m][h*8+c]
            int m = tid - 128;
            const float* src = &Wp[(size_t)m * 256 + h*8];
            float4 w0 = *(const float4*)(src);
            float4 w1 = *(const float4*)(src + 4);
            Ws[0][m] = w0.x; Ws[1][m] = w0.y; Ws[2][m] = w0.z; Ws[3][m] = w0.w;
            Ws[4][m] = w1.x; Ws[5][m] = w1.y; Ws[6][m] = w1.z; Ws[7][m] = w1.w;
        }
        __syncthreads();
        if (tid < 128) {
            // compute o for pixel p0+tid, head h
            int n = p0 + tid;
            size_t base = ((size_t)bh * NP + n) * 8;
            float qv[8];
            *(float4*)(qv)   = *(const float4*)&q[base];
            *(float4*)(qv+4) = *(const float4*)&q[base+4];
            float s1 = EPSF, csk = EPSF;
            #pragma unroll
            for (int d = 0; d < 8; d++) {
                s1  = fmaf(qv[d] + EPSF, hs[64 + d] + EPSF, s1);
                csk = fmaf(qv[d] + EPSF, hs[72 + d] + EPSF, csk);
            }
            float siv = 1.f / s1;
            float alloc = sigmoidf_(csk);
            float scl = siv * alloc;
            float o8[8];
            float mu = 0.f;
            #pragma unroll
            for (int e = 0; e < 8; e++) {
                float s = 0.f;
                #pragma unroll
                for (int d = 0; d < 8; d++) s = fmaf(qv[d], hs[d*8 + e], s);
                o8[e] = s * scl;
                mu += o8[e];
            }
            mu *= 0.125f;
            float var = 0.f;
            #pragma unroll
            for (int e = 0; e < 8; e++) { float dd = o8[e] - mu; var = fmaf(dd, dd, var); }
            var *= 0.125f;
            float wv = rsqrtf(var + 1e-5f);
            #pragma unroll
            for (int e = 0; e < 8; e++)
                Xs[e][tid] = (o8[e] - mu) * wv * lg[e] + lb[e];
        }
        __syncthreads();
        #pragma unroll
        for (int kk = 0; kk < 8; kk++) {
            float a[8], bb[8];
            *(float4*)(a)   = *(const float4*)&Ws[kk][ty*8];
            *(float4*)(a+4) = *(const float4*)&Ws[kk][ty*8+4];
            *(float4*)(bb)  = *(const float4*)&Xs[kk][tx*8];
            *(float4*)(bb+4)= *(const float4*)&Xs[kk][tx*8+4];
            #pragma unroll
            for (int i = 0; i < 8; i++)
                #pragma unroll
                for (int j = 0; j < 8; j++)
                    acc[i][j] = fmaf(a[i], bb[j], acc[i][j]);
        }
    }

    float* Yb = Y + (size_t)b * 128 * NP;
    #pragma unroll
    for (int i = 0; i < 8; i++) {
        int m = ty*8 + i;
        float sc = bng[m] * rsqrtf(bnv[m] + 1e-5f);
        float mm = bnm[m];
        float bi = bnb[m];
        float r[8];
        #pragma unroll
        for (int j = 0; j < 8; j++) r[j] = (acc[i][j] - mm) * sc + bi;
        float* dst = &Yb[(size_t)m * NP + p0 + tx*8];
        *(float4*)(dst)   = make_float4(r[0], r[1], r[2], r[3]);
        *(float4*)(dst+4) = make_float4(r[4], r[5], r[6], r[7]);
    }
}

// =================================================================================
extern "C" void kernel_launch(void* const* d_in, const int* in_sizes, int n_in,
                              void* d_out, int out_size) {
    const float* x    = (const float*)d_in[0];
    const float* edge = (const float*)d_in[1];
    const float* Wq   = (const float*)d_in[2];
    const float* Wkv  = (const float*)d_in[3];
    const float* dwq  = (const float*)d_in[4];
    const float* pwq  = (const float*)d_in[5];
    const float* dwkv = (const float*)d_in[6];
    const float* pwkv = (const float*)d_in[7];
    const float* ln_g = (const float*)d_in[8];
    const float* ln_b = (const float*)d_in[9];
    const float* Wp   = (const float*)d_in[10];
    const float* bn_g = (const float*)d_in[11];
    const float* bn_b = (const float*)d_in[12];
    const float* bn_m = (const float*)d_in[13];
    const float* bn_v = (const float*)d_in[14];

    float *q0, *kv0, *qb, *kb, *vb, *stats, *hstats;
    cudaGetSymbolAddress((void**)&q0,     g_q0);
    cudaGetSymbolAddress((void**)&kv0,    g_kv0);
    cudaGetSymbolAddress((void**)&qb,     g_q);
    cudaGetSymbolAddress((void**)&kb,     g_k);
    cudaGetSymbolAddress((void**)&vb,     g_v);
    cudaGetSymbolAddress((void**)&stats,  g_stats);
    cudaGetSymbolAddress((void**)&hstats, g_hstats);

    k_zero<<<8, 1024>>>(stats, 64*128);

    // q0 = Wq @ edge ; kv0 = Wkv @ x
    k_gemm<<<dim3(512,1,2), 256>>>(Wq,  edge, q0,  128, 128);
    k_gemm<<<dim3(512,2,2), 256>>>(Wkv, x,    kv0, 256, 128);

    // fused dw + gconv + sigmoid + stats
    k_fq <<<dim3(8,8,32), dim3(32,8)>>>(q0,  dwq,  pwq,  qb, stats);
    k_fkv<<<dim3(8,8,32), dim3(32,8)>>>(kv0, dwkv, pwkv, kb, vb, stats);

    // sink_incoming / source_outgoing reductions
    k_siso<<<dim3(64,32,2), 256>>>(qb, kb, stats);

    // Z + kvm
    k_kvm<<<dim3(8,32,2), 256>>>(kb, vb, stats);

    // pack per-head constants
    k_prep<<<64, 80>>>(stats, hstats);

    // fused attention-epilogue + projection + batchnorm -> d_out [b][128][n]
    k_gemm_proj<<<dim3(512,1,2), 256>>>(Wp, qb, hstats, ln_g, ln_b,
                                        bn_g, bn_b, bn_m, bn_v, (float*)d_out);
}

// round 5
// speedup vs baseline: 1.1066x; 1.1066x over previous
#include <cuda_runtime.h>
#include <math.h>
#include <stdint.h>

#define NP 65536
#define EPSF 1e-6f

// ---------------- scratch (static device allocations; no cudaMalloc) -------------
__device__ float g_q0 [2*128*NP];   // conv1x1(edge, Wq)
__device__ float g_kv0[2*256*NP];   // conv1x1(x, Wkv)
__device__ float g_q  [2*32*NP*8];  // sigmoid(q)  [b][h][n][d]
__device__ float g_k  [2*32*NP*8];  // sigmoid(k)
__device__ float g_v  [2*32*NP*8];  // v (raw)
__device__ float g_o  [2*256*NP];   // pre-projection output [b][c][n]
__device__ float g_stats[64*128];   // per (b,h): [0:8) qsum [8:16) ksum [16:24) qsi [24:32) kso [32] Z [40:104) kvm

__device__ __forceinline__ float sigmoidf_(float x){
    return __fdividef(1.f, 1.f + __expf(-x));
}

// ---------------- zero stats -------------
__global__ void k_zero(float* __restrict__ p, int n){
    int i = blockIdx.x*blockDim.x + threadIdx.x;
    if (i < n) p[i] = 0.f;
}

// ---------------- tensor-core GEMM (tf32 3-pass split, fp32-grade accuracy) -------
// Y[b][m][p] = sum_k A[m][k] * X[b][k][p], optional BN epilogue.
// Block tile 128(M) x 64(P), K-chunk 16, 8 warps of 32x32.
#define MMA_TF32(d, a0,a1,a2,a3, b0,b1) \
    asm volatile("mma.sync.aligned.m16n8k8.row.col.f32.tf32.tf32.f32 " \
        "{%0,%1,%2,%3}, {%4,%5,%6,%7}, {%8,%9}, {%0,%1,%2,%3};" \
        : "+f"(d[0]), "+f"(d[1]), "+f"(d[2]), "+f"(d[3]) \
        : "r"(a0), "r"(a1), "r"(a2), "r"(a3), "r"(b0), "r"(b1))

__device__ __forceinline__ void tf32_split(float x, float& hi, float& lo){
    uint32_t uh, ul;
    asm("cvt.rna.tf32.f32 %0, %1;" : "=r"(uh) : "f"(x));
    float h = __uint_as_float(uh);
    float l = x - h;                       // exact in fp32
    asm("cvt.rna.tf32.f32 %0, %1;" : "=r"(ul) : "f"(l));
    hi = h; lo = __uint_as_float(ul);
}

__global__ __launch_bounds__(256) void k_gemm_tc(
    const float* __restrict__ A, const float* __restrict__ X, float* __restrict__ Y,
    int M, int K,
    const float* __restrict__ bng, const float* __restrict__ bnb,
    const float* __restrict__ bnm, const float* __restrict__ bnv)
{
    __shared__ float As_hi[16][136], As_lo[16][136];
    __shared__ float Bs_hi[16][72],  Bs_lo[16][72];
    const int b  = blockIdx.z;
    const int m0 = blockIdx.y * 128;
    const int p0 = blockIdx.x * 64;
    const float* Xb = X + (size_t)b * K * NP;
    float*       Yb = Y + (size_t)b * M * NP;
    const int tid  = threadIdx.x;
    const int lane = tid & 31, warp = tid >> 5;
    const int wm = warp >> 1, wn = warp & 1;
    const int lg = lane >> 2, lt = lane & 3;

    // global-load assignments
    const int am = tid >> 1;            // 0..127 (m row)
    const int ak = (tid & 1) * 8;       // k sub-offset 0/8
    const int xr = tid >> 4;            // 0..15 (k row)
    const int xc = (tid & 15) * 4;      // 0..60 (pixel col)

    float acc[2][4][4];
    #pragma unroll
    for (int i = 0; i < 2; i++)
        #pragma unroll
        for (int j = 0; j < 4; j++)
            #pragma unroll
            for (int r = 0; r < 4; r++) acc[i][j][r] = 0.f;

    float aReg[8]; float4 xReg;
    {
        const float* ap = &A[(size_t)(m0 + am) * K + ak];
        float4 v0 = *(const float4*)ap, v1 = *(const float4*)(ap + 4);
        aReg[0]=v0.x; aReg[1]=v0.y; aReg[2]=v0.z; aReg[3]=v0.w;
        aReg[4]=v1.x; aReg[5]=v1.y; aReg[6]=v1.z; aReg[7]=v1.w;
        xReg = *(const float4*)&Xb[(size_t)xr * NP + p0 + xc];
    }

    const int nch = K >> 4;
    for (int ch = 0; ch < nch; ch++) {
        // split + store current chunk to smem
        #pragma unroll
        for (int i = 0; i < 8; i++) {
            float hi, lo; tf32_split(aReg[i], hi, lo);
            As_hi[ak + i][am] = hi; As_lo[ak + i][am] = lo;
        }
        {
            float xs[4] = {xReg.x, xReg.y, xReg.z, xReg.w};
            #pragma unroll
            for (int i = 0; i < 4; i++) {
                float hi, lo; tf32_split(xs[i], hi, lo);
                Bs_hi[xr][xc + i] = hi; Bs_lo[xr][xc + i] = lo;
            }
        }
        __syncthreads();
        // prefetch next chunk
        if (ch + 1 < nch) {
            int k0 = (ch + 1) * 16;
            const float* ap = &A[(size_t)(m0 + am) * K + k0 + ak];
            float4 v0 = *(const float4*)ap, v1 = *(const float4*)(ap + 4);
            aReg[0]=v0.x; aReg[1]=v0.y; aReg[2]=v0.z; aReg[3]=v0.w;
            aReg[4]=v1.x; aReg[5]=v1.y; aReg[6]=v1.z; aReg[7]=v1.w;
            xReg = *(const float4*)&Xb[(size_t)(k0 + xr) * NP + p0 + xc];
        }
        // compute: 2 k8-steps
        #pragma unroll
        for (int ks = 0; ks < 2; ks++) {
            const int kr = ks * 8;
            uint32_t ah[2][4], al[2][4];
            #pragma unroll
            for (int tm = 0; tm < 2; tm++) {
                int mb = wm*32 + tm*16 + lg;
                int r  = kr + lt;
                ah[tm][0] = __float_as_uint(As_hi[r  ][mb]);
                ah[tm][1] = __float_as_uint(As_hi[r  ][mb+8]);
                ah[tm][2] = __float_as_uint(As_hi[r+4][mb]);
                ah[tm][3] = __float_as_uint(As_hi[r+4][mb+8]);
                al[tm][0] = __float_as_uint(As_lo[r  ][mb]);
                al[tm][1] = __float_as_uint(As_lo[r  ][mb+8]);
                al[tm][2] = __float_as_uint(As_lo[r+4][mb]);
                al[tm][3] = __float_as_uint(As_lo[r+4][mb+8]);
            }
            #pragma unroll
            for (int tn = 0; tn < 4; tn++) {
                int nb = wn*32 + tn*8 + lg;
                uint32_t bh0 = __float_as_uint(Bs_hi[kr   + lt][nb]);
                uint32_t bh1 = __float_as_uint(Bs_hi[kr+4 + lt][nb]);
                uint32_t bl0 = __float_as_uint(Bs_lo[kr   + lt][nb]);
                uint32_t bl1 = __float_as_uint(Bs_lo[kr+4 + lt][nb]);
                #pragma unroll
                for (int tm = 0; tm < 2; tm++) {
                    MMA_TF32(acc[tm][tn], ah[tm][0], ah[tm][1], ah[tm][2], ah[tm][3], bh0, bh1);
                    MMA_TF32(acc[tm][tn], ah[tm][0], ah[tm][1], ah[tm][2], ah[tm][3], bl0, bl1);
                    MMA_TF32(acc[tm][tn], al[tm][0], al[tm][1], al[tm][2], al[tm][3], bh0, bh1);
                }
            }
        }
        __syncthreads();
    }

    // epilogue (+ optional BN)
    #pragma unroll
    for (int tm = 0; tm < 2; tm++) {
        int r0 = m0 + wm*32 + tm*16 + lg;
        int r1 = r0 + 8;
        float sc0 = 1.f, mm0 = 0.f, bi0 = 0.f, sc1 = 1.f, mm1 = 0.f, bi1 = 0.f;
        if (bng) {
            sc0 = bng[r0] * rsqrtf(bnv[r0] + 1e-5f); mm0 = bnm[r0]; bi0 = bnb[r0];
            sc1 = bng[r1] * rsqrtf(bnv[r1] + 1e-5f); mm1 = bnm[r1]; bi1 = bnb[r1];
        }
        #pragma unroll
        for (int tn = 0; tn < 4; tn++) {
            int c = p0 + wn*32 + tn*8 + lt*2;
            float d0 = acc[tm][tn][0], d1 = acc[tm][tn][1];
            float d2 = acc[tm][tn][2], d3 = acc[tm][tn][3];
            if (bng) {
                d0 = (d0 - mm0) * sc0 + bi0; d1 = (d1 - mm0) * sc0 + bi0;
                d2 = (d2 - mm1) * sc1 + bi1; d3 = (d3 - mm1) * sc1 + bi1;
            }
            *(float2*)&Yb[(size_t)r0 * NP + c] = make_float2(d0, d1);
            *(float2*)&Yb[(size_t)r1 * NP + c] = make_float2(d2, d3);
        }
    }
}

// ---------------- fused q build: dw5x5 + gconv + sigmoid + qsum --------------------
__global__ __launch_bounds__(256) void k_fq(
    const float* __restrict__ q0, const float* __restrict__ dwq,
    const float* __restrict__ pwq, float* __restrict__ qout, float* __restrict__ stats)
{
    const int g = blockIdx.z & 15;
    const int b = blockIdx.z >> 4;
    const int x0 = blockIdx.x * 32, y0 = blockIdx.y * 32;
    __shared__ float sm[8][36][40];
    __shared__ float pw[64];
    __shared__ float kwsm[200];
    __shared__ float red[128];
    const int tid = threadIdx.y * 32 + threadIdx.x;
    if (tid < 64)  pw[tid]   = pwq[g*64 + tid];
    if (tid < 200) kwsm[tid] = dwq[g*200 + tid];

    const float* base = q0 + (size_t)(b*128 + g*8) * NP;
    for (int idx = tid; idx < 8*36*36; idx += 256) {
        int c   = idx / 1296;
        int rem = idx - c*1296;
        int r   = rem / 36;
        int col = rem - r*36;
        int gy = y0 + r - 2, gx = x0 + col - 2;
        float v = 0.f;
        if ((unsigned)gy < 256u && (unsigned)gx < 256u)
            v = base[(size_t)c*NP + gy*256 + gx];
        sm[c][r][col] = v;
    }
    __syncthreads();

    const int tx = threadIdx.x;
    const int ly0 = threadIdx.y * 4;

    float dwv[8][4];
    #pragma unroll
    for (int c = 0; c < 8; c++) {
        float kw[25];
        #pragma unroll
        for (int t = 0; t < 25; t++) kw[t] = kwsm[c*25 + t];
        float a0=0.f,a1=0.f,a2=0.f,a3=0.f;
        #pragma unroll
        for (int r = 0; r < 8; r++) {
            float v0 = sm[c][ly0+r][tx+0];
            float v1 = sm[c][ly0+r][tx+1];
            float v2 = sm[c][ly0+r][tx+2];
            float v3 = sm[c][ly0+r][tx+3];
            float v4 = sm[c][ly0+r][tx+4];
            #pragma unroll
            for (int j = 0; j < 4; j++) {
                int ky = r - j;
                if (ky >= 0 && ky < 5) {
                    float s = kw[ky*5+0]*v0 + kw[ky*5+1]*v1 + kw[ky*5+2]*v2
                            + kw[ky*5+3]*v3 + kw[ky*5+4]*v4;
                    if (j == 0) a0 += s; else if (j == 1) a1 += s;
                    else if (j == 2) a2 += s; else a3 += s;
                }
            }
        }
        dwv[c][0]=a0; dwv[c][1]=a1; dwv[c][2]=a2; dwv[c][3]=a3;
    }

    float sdir[8], sms[8];
    #pragma unroll
    for (int d = 0; d < 8; d++) { sdir[d]=0.f; sms[d]=0.f; }

    #pragma unroll
    for (int j = 0; j < 4; j++) {
        int n = (y0 + ly0 + j) * 256 + x0 + tx;
        float dir[8], msd[8];
        #pragma unroll
        for (int d = 0; d < 8; d++) {
            dir[d] = sigmoidf_(sm[d][ly0+j+2][tx+2]);
            float s = 0.f;
            #pragma unroll
            for (int i = 0; i < 8; i++) s = fmaf(pw[d*8+i], dwv[i][j], s);
            msd[d] = sigmoidf_(s);
            sdir[d] += dir[d];
            sms[d]  += msd[d];
        }
        float4* d0 = (float4*)&qout[((size_t)(b*32 + g) * NP + n) * 8];
        d0[0] = make_float4(dir[0],dir[1],dir[2],dir[3]);
        d0[1] = make_float4(dir[4],dir[5],dir[6],dir[7]);
        float4* d1 = (float4*)&qout[((size_t)(b*32 + 16 + g) * NP + n) * 8];
        d1[0] = make_float4(msd[0],msd[1],msd[2],msd[3]);
        d1[1] = make_float4(msd[4],msd[5],msd[6],msd[7]);
    }

    float vals[16];
    #pragma unroll
    for (int d = 0; d < 8; d++) { vals[d] = sdir[d]; vals[8+d] = sms[d]; }
    #pragma unroll
    for (int i = 0; i < 16; i++)
        for (int off = 16; off; off >>= 1) vals[i] += __shfl_down_sync(~0u, vals[i], off);
    int lane = tid & 31, w = tid >> 5;
    if (lane == 0)
        #pragma unroll
        for (int i = 0; i < 16; i++) red[w*16 + i] = vals[i];
    __syncthreads();
    if (tid < 16) {
        float t = 0.f;
        #pragma unroll
        for (int w2 = 0; w2 < 8; w2++) t += red[w2*16 + tid];
        int h = (tid < 8) ? g : (16 + g);
        atomicAdd(&stats[(b*32 + h)*128 + (tid & 7)], t);
    }
}

// ---------------- fused kv build: dw5x5 + gconv, k=sigmoid+ksum, v raw -------------
__global__ __launch_bounds__(256) void k_fkv(
    const float* __restrict__ kv0, const float* __restrict__ dwkv,
    const float* __restrict__ pwkv, float* __restrict__ kout, float* __restrict__ vout,
    float* __restrict__ stats)
{
    const int g = blockIdx.z & 15;
    const int b = blockIdx.z >> 4;
    const int x0 = blockIdx.x * 32, y0 = blockIdx.y * 32;
    __shared__ float sm[8][36][40];
    __shared__ float pw[128];
    __shared__ float kwsm[400];
    __shared__ float red[128];
    const int tid = threadIdx.y * 32 + threadIdx.x;
    if (tid < 128) pw[tid] = pwkv[g*128 + tid];
    for (int t = tid; t < 400; t += 256) kwsm[t] = dwkv[g*400 + t];

    const int tx = threadIdx.x;
    const int ly0 = threadIdx.y * 4;
    float ksum[16];
    #pragma unroll
    for (int i = 0; i < 16; i++) ksum[i] = 0.f;

    #pragma unroll
    for (int half = 0; half < 2; half++) {
        const float* base = kv0 + (size_t)(b*256 + g*16 + half*8) * NP;
        __syncthreads();
        for (int idx = tid; idx < 8*36*36; idx += 256) {
            int c   = idx / 1296;
            int rem = idx - c*1296;
            int r   = rem / 36;
            int col = rem - r*36;
            int gy = y0 + r - 2, gx = x0 + col - 2;
            float v = 0.f;
            if ((unsigned)gy < 256u && (unsigned)gx < 256u)
                v = base[(size_t)c*NP + gy*256 + gx];
            sm[c][r][col] = v;
        }
        __syncthreads();

        float dwv[8][4];
        #pragma unroll
        for (int c = 0; c < 8; c++) {
            float kw[25];
            #pragma unroll
            for (int t = 0; t < 25; t++) kw[t] = kwsm[half*200 + c*25 + t];
            float a0=0.f,a1=0.f,a2=0.f,a3=0.f;
            #pragma unroll
            for (int r = 0; r < 8; r++) {
                float v0 = sm[c][ly0+r][tx+0];
                float v1 = sm[c][ly0+r][tx+1];
                float v2 = sm[c][ly0+r][tx+2];
                float v3 = sm[c][ly0+r][tx+3];
                float v4 = sm[c][ly0+r][tx+4];
                #pragma unroll
                for (int j = 0; j < 4; j++) {
                    int ky = r - j;
                    if (ky >= 0 && ky < 5) {
                        float s = kw[ky*5+0]*v0 + kw[ky*5+1]*v1 + kw[ky*5+2]*v2
                                + kw[ky*5+3]*v3 + kw[ky*5+4]*v4;
                        if (j == 0) a0 += s; else if (j == 1) a1 += s;
                        else if (j == 2) a2 += s; else a3 += s;
                    }
                }
            }
            dwv[c][0]=a0; dwv[c][1]=a1; dwv[c][2]=a2; dwv[c][3]=a3;
        }

        float* out = half == 0 ? kout : vout;
        #pragma unroll
        for (int j = 0; j < 4; j++) {
            int n = (y0 + ly0 + j) * 256 + x0 + tx;
            float dir[8], msd[8];
            #pragma unroll
            for (int d = 0; d < 8; d++) {
                float dv = sm[d][ly0+j+2][tx+2];
                float s = 0.f;
                #pragma unroll
                for (int i = 0; i < 8; i++) s = fmaf(pw[half*64 + d*8+i], dwv[i][j], s);
                if (half == 0) {
                    dv = sigmoidf_(dv); s = sigmoidf_(s);
                    ksum[d] += dv; ksum[8+d] += s;
                }
                dir[d] = dv; msd[d] = s;
            }
            float4* d0 = (float4*)&out[((size_t)(b*32 + g) * NP + n) * 8];
            d0[0] = make_float4(dir[0],dir[1],dir[2],dir[3]);
            d0[1] = make_float4(dir[4],dir[5],dir[6],dir[7]);
            float4* d1 = (float4*)&out[((size_t)(b*32 + 16 + g) * NP + n) * 8];
            d1[0] = make_float4(msd[0],msd[1],msd[2],msd[3]);
            d1[1] = make_float4(msd[4],msd[5],msd[6],msd[7]);
        }
    }

    #pragma unroll
    for (int i = 0; i < 16; i++)
        for (int off = 16; off; off >>= 1) ksum[i] += __shfl_down_sync(~0u, ksum[i], off);
    int lane = tid & 31, w = tid >> 5;
    if (lane == 0)
        #pragma unroll
        for (int i = 0; i < 16; i++) red[w*16 + i] = ksum[i];
    __syncthreads();
    if (tid < 16) {
        float t = 0.f;
        #pragma unroll
        for (int w2 = 0; w2 < 8; w2++) t += red[w2*16 + tid];
        int h = (tid < 8) ? g : (16 + g);
        atomicAdd(&stats[(b*32 + h)*128 + 8 + (tid & 7)], t);
    }
}

// ---------------- sink_incoming/source_outgoing reductions --------
__global__ __launch_bounds__(256) void k_siso(
    const float* __restrict__ q, const float* __restrict__ k, float* __restrict__ stats)
{
    const int h = blockIdx.y, b = blockIdx.z;
    const int bh = b*32 + h;
    const int tid = threadIdx.x;
    __shared__ float qs[8], ks[8];
    __shared__ float red[128];
    if (tid < 8)  qs[tid] = stats[bh*128 + tid];
    else if (tid < 16) ks[tid-8] = stats[bh*128 + tid];
    __syncthreads();

    float aq[8], ak[8];
    #pragma unroll
    for (int d = 0; d < 8; d++) { aq[d] = 0.f; ak[d] = 0.f; }
    const int nbase = blockIdx.x * 1024;

    for (int it = 0; it < 4; it++) {
        int n = nbase + it*256 + tid;
        size_t base = ((size_t)bh * NP + n) * 8;
        float qv[8], kv_[8];
        *(float4*)(qv)    = *(const float4*)&q[base];
        *(float4*)(qv+4)  = *(const float4*)&q[base+4];
        *(float4*)(kv_)   = *(const float4*)&k[base];
        *(float4*)(kv_+4) = *(const float4*)&k[base+4];
        float s1 = EPSF, s2 = EPSF;
        #pragma unroll
        for (int d = 0; d < 8; d++) {
            s1 = fmaf(qv[d] + EPSF, ks[d] + EPSF, s1);
            s2 = fmaf(kv_[d] + EPSF, qs[d] + EPSF, s2);
        }
        float siv = 1.f / s1;
        float sov = 1.f / s2;
        #pragma unroll
        for (int d = 0; d < 8; d++) { aq[d] = fmaf(qv[d], siv, aq[d]); ak[d] = fmaf(kv_[d], sov, ak[d]); }
    }
    float vals[16];
    #pragma unroll
    for (int d = 0; d < 8; d++) { vals[d] = aq[d]; vals[8+d] = ak[d]; }
    #pragma unroll
    for (int i = 0; i < 16; i++)
        for (int off = 16; off; off >>= 1) vals[i] += __shfl_down_sync(~0u, vals[i], off);
    int lane = tid & 31, w = tid >> 5;
    if (lane == 0)
        #pragma unroll
        for (int i = 0; i < 16; i++) red[w*16 + i] = vals[i];
    __syncthreads();
    if (tid < 16) {
        float t = 0.f;
        #pragma unroll
        for (int w2 = 0; w2 < 8; w2++) t += red[w2*16 + tid];
        atomicAdd(&stats[bh*128 + 16 + tid], t);
    }
}

// ---------------- Z and kvm accumulation ----------------
__global__ __launch_bounds__(256) void k_kvm(
    const float* __restrict__ k, const float* __restrict__ v, float* __restrict__ stats)
{
    const int h = blockIdx.y, b = blockIdx.z;
    const int bh = b*32 + h;
    const int tid = threadIdx.x;
    __shared__ float qsi[8];
    __shared__ float red[8*65];
    if (tid < 8) qsi[tid] = stats[bh*128 + 16 + tid];
    __syncthreads();

    float acc[64];
    #pragma unroll
    for (int i = 0; i < 64; i++) acc[i] = 0.f;
    float zl = 0.f;
    const int nbase = blockIdx.x * 8192;

    for (int it = 0; it < 32; it++) {
        int n = nbase + it*256 + tid;
        size_t base = ((size_t)bh * NP + n) * 8;
        float kv_[8], vv[8];
        *(float4*)(kv_)   = *(const float4*)&k[base];
        *(float4*)(kv_+4) = *(const float4*)&k[base+4];
        *(float4*)(vv)    = *(const float4*)&v[base];
        *(float4*)(vv+4)  = *(const float4*)&v[base+4];
        float cs = EPSF;
        #pragma unroll
        for (int d = 0; d < 8; d++) cs = fmaf(kv_[d] + EPSF, qsi[d] + EPSF, cs);
        cs = fminf(fmaxf(cs, -1.f), 1.f);
        float ex = __expf(cs);
        zl += ex;
        #pragma unroll
        for (int e = 0; e < 8; e++) {
            float ve = vv[e] * ex;
            #pragma unroll
            for (int d = 0; d < 8; d++)
                acc[d*8 + e] = fmaf(kv_[d], ve, acc[d*8 + e]);
        }
    }
    #pragma unroll
    for (int i = 0; i < 64; i++)
        for (int off = 16; off; off >>= 1) acc[i] += __shfl_down_sync(~0u, acc[i], off);
    for (int off = 16; off; off >>= 1) zl += __shfl_down_sync(~0u, zl, off);
    int lane = tid & 31, w = tid >> 5;
    if (lane == 0) {
        #pragma unroll
        for (int i = 0; i < 64; i++) red[w*65 + i] = acc[i];
        red[w*65 + 64] = zl;
    }
    __syncthreads();
    if (tid < 65) {
        float t = 0.f;
        #pragma unroll
        for (int w2 = 0; w2 < 8; w2++) t += red[w2*65 + tid];
        atomicAdd(&stats[bh*128 + (tid < 64 ? 40 + tid : 32)], t);
    }
}

// ---------------- out = LN( (q @ kvm) * si * sigmoid(csink) ) -> [b][c][n] ----
__global__ __launch_bounds__(256) void k_out(
    const float* __restrict__ q, const float* __restrict__ stats,
    const float* __restrict__ ln_g, const float* __restrict__ ln_b, float* __restrict__ o)
{
    const int h = blockIdx.y, b = blockIdx.z;
    const int bh = b*32 + h;
    const int tid = threadIdx.x;
    __shared__ float kvs[64];
    __shared__ float kso[8], ks[8], lg[8], lb[8];
    if (tid < 64) {
        float z = stats[bh*128 + 32];
        kvs[tid] = stats[bh*128 + 40 + tid] * (65536.f / z);
    }
    if (tid < 8) {
        kso[tid] = stats[bh*128 + 24 + tid];
        ks[tid]  = stats[bh*128 + 8 + tid];
        lg[tid] = ln_g[tid]; lb[tid] = ln_b[tid];
    }
    __syncthreads();

    const int nbase = blockIdx.x * 1024;
    for (int it = 0; it < 4; it++) {
        int n = nbase + it*256 + tid;
        size_t base = ((size_t)bh * NP + n) * 8;
        float qv[8];
        *(float4*)(qv)   = *(const float4*)&q[base];
        *(float4*)(qv+4) = *(const float4*)&q[base+4];
        float s1 = EPSF, csk = EPSF;
        #pragma unroll
        for (int d = 0; d < 8; d++) {
            s1  = fmaf(qv[d] + EPSF, ks[d]  + EPSF, s1);
            csk = fmaf(qv[d] + EPSF, kso[d] + EPSF, csk);
        }
        float siv = 1.f / s1;
        float alloc = sigmoidf_(csk);
        float scl = siv * alloc;
        float o8[8];
        float mu = 0.f;
        #pragma unroll
        for (int e = 0; e < 8; e++) {
            float s = 0.f;
            #pragma unroll
            for (int d = 0; d < 8; d++) s = fmaf(qv[d], kvs[d*8 + e], s);
            o8[e] = s * scl;
            mu += o8[e];
        }
        mu *= 0.125f;
        float var = 0.f;
        #pragma unroll
        for (int e = 0; e < 8; e++) { float dd = o8[e] - mu; var = fmaf(dd, dd, var); }
        var *= 0.125f;
        float wv = rsqrtf(var + 1e-5f);
        #pragma unroll
        for (int e = 0; e < 8; e++)
            o[(size_t)(b*256 + h*8 + e) * NP + n] = (o8[e] - mu) * wv * lg[e] + lb[e];
    }
}

// =================================================================================
extern "C" void kernel_launch(void* const* d_in, const int* in_sizes, int n_in,
                              void* d_out, int out_size) {
    const float* x    = (const float*)d_in[0];
    const float* edge = (const float*)d_in[1];
    const float* Wq   = (const float*)d_in[2];
    const float* Wkv  = (const float*)d_in[3];
    const float* dwq  = (const float*)d_in[4];
    const float* pwq  = (const float*)d_in[5];
    const float* dwkv = (const float*)d_in[6];
    const float* pwkv = (const float*)d_in[7];
    const float* ln_g = (const float*)d_in[8];
    const float* ln_b = (const float*)d_in[9];
    const float* Wp   = (const float*)d_in[10];
    const float* bn_g = (const float*)d_in[11];
    const float* bn_b = (const float*)d_in[12];
    const float* bn_m = (const float*)d_in[13];
    const float* bn_v = (const float*)d_in[14];

    float *q0, *kv0, *qb, *kb, *vb, *ob, *stats;
    cudaGetSymbolAddress((void**)&q0,    g_q0);
    cudaGetSymbolAddress((void**)&kv0,   g_kv0);
    cudaGetSymbolAddress((void**)&qb,    g_q);
    cudaGetSymbolAddress((void**)&kb,    g_k);
    cudaGetSymbolAddress((void**)&vb,    g_v);
    cudaGetSymbolAddress((void**)&ob,    g_o);
    cudaGetSymbolAddress((void**)&stats, g_stats);

    k_zero<<<8, 1024>>>(stats, 64*128);

    // q0 = Wq @ edge ; kv0 = Wkv @ x   (tensor-core tf32 3-pass)
    k_gemm_tc<<<dim3(1024,1,2), 256>>>(Wq,  edge, q0,  128, 128, nullptr, nullptr, nullptr, nullptr);
    k_gemm_tc<<<dim3(1024,2,2), 256>>>(Wkv, x,    kv0, 256, 128, nullptr, nullptr, nullptr, nullptr);

    // fused dw + gconv + sigmoid + stats
    k_fq <<<dim3(8,8,32), dim3(32,8)>>>(q0,  dwq,  pwq,  qb, stats);
    k_fkv<<<dim3(8,8,32), dim3(32,8)>>>(kv0, dwkv, pwkv, kb, vb, stats);

    // sink_incoming / source_outgoing reductions
    k_siso<<<dim3(64,32,2), 256>>>(qb, kb, stats);

    // Z + kvm
    k_kvm<<<dim3(8,32,2), 256>>>(kb, vb, stats);

    // attention output + layernorm -> [b][256][n]
    k_out<<<dim3(64,32,2), 256>>>(qb, stats, ln_g, ln_b, ob);

    // projection + batchnorm -> d_out [b][128][n]  (tensor-core)
    k_gemm_tc<<<dim3(1024,1,2), 256>>>(Wp, ob, (float*)d_out, 128, 256, bn_g, bn_b, bn_m, bn_v);
}